// round 12
// baseline (speedup 1.0000x reference)
#include <cuda_runtime.h>
#include <math.h>

#define Bn    8
#define NPIX  (512*512)
#define NBINS 256

#define OFF0 0u
#define OFF1 2097152u
#define OFF2 2621440u
#define OFF3 2752512u
#define OFF4 2785280u

#define G0 0.12007823f
#define G1 0.23388087f
#define G2 0.29208180f
__device__ __constant__ float c_g[5] = {G0, G1, G2, G1, G0};

// interleaved pyramid: d_L[i] = (pred_L, tgt_L)
__device__ float2 d_L[2793472];
__device__ int    d_histd[Bn*3*NBINS];     // signed: pred minus tgt counts
__device__ float  d_l1sum;
__device__ float  d_ssim_sum[Bn*5];
__device__ float  d_cs_sum[Bn*5];
__device__ float  d_l1img[Bn];
__device__ unsigned g_cnt[Bn][5];
__device__ unsigned g_final;

__device__ __forceinline__ unsigned ld_cg(const unsigned* p)
{
    unsigned v;
    asm volatile("ld.global.cg.u32 %0, [%1];" : "=r"(v) : "l"(p) : "memory");
    return v;
}

// ---------------- RGB -> normalized LAB -------------------------------------
__device__ __forceinline__ float srgb_lin(float x)
{
    if (x <= 0.04045f) return x * (1.f/12.92f);
    float y = (fmaxf(x, 1e-4f) + 0.055f) * (1.f/1.055f);
    return __powf(y, 2.4f);
}

__device__ __forceinline__ float f_lab(float t)
{
    const float e3 = 0.008856451679035631f;
    if (t <= e3) return t * (841.f/108.f) + (4.f/29.f);
    return __powf(fmaxf(t, 1e-4f), 1.f/3.f);
}

__device__ __forceinline__ void rgb2lab_norm(float r, float g, float b,
                                             float& L, float& A, float& Bc)
{
    float lr = srgb_lin(r), lg = srgb_lin(g), lb = srgb_lin(b);
    float X = lr*0.412453f + lg*0.357580f + lb*0.180423f;
    float Y = lr*0.212671f + lg*0.715160f + lb*0.072169f;
    float Z = lr*0.019334f + lg*0.119193f + lb*0.950227f;
    X *= (1.f/0.950456f);
    Z *= (1.f/1.088754f);
    float fx = f_lab(X), fy = f_lab(Y), fz = f_lab(Z);
    float Ll = 116.f*fy - 16.f;
    float Aa = 500.f*(fx - fy);
    float Bb = 200.f*(fy - fz);
    L  = fminf(fmaxf(Ll * 0.01f,                 0.f), 1.f);
    A  = fminf(fmaxf((Aa*(1.f/110.f)+1.f)*0.5f,  0.f), 1.f);
    Bc = fminf(fmaxf((Bb*(1.f/110.f)+1.f)*0.5f,  0.f), 1.f);
}

__device__ __forceinline__ int bin_of(float v)
{
    int b = (int)(v * 256.f);
    return b > 255 ? 255 : b;
}

// ---------------- shared memory ----------------------------------------------
struct Unit {
    float2 t[36][36];
    float2 m12[36][32];
    float2 x12[36][32];
    float  a12[36][32];
    float  redS[8], redC[8];
};

struct LabSh {
    int   hist[3*NBINS];
    float red[8];
};

union ShMem {
    Unit  u;
    LabSh lab;
};

// ---------------- 32x32 SSIM tile (256 threads, block == unit) --------------
__device__ __forceinline__ void ssim_tile32(Unit& U, int ut,
                                            unsigned off, unsigned offo,
                                            int Hl, int b, int tix, int tiy,
                                            bool pool, float& accS, float& accC)
{
    const float2* src = d_L + off + (size_t)b*Hl*Hl;
    int ox = tix*32, oy = tiy*32;

    for (int i = ut; i < 36*36; i += 256) {
        int r = i/36, c = i%36;
        int gy = oy + r - 2, gx = ox + c - 2;
        float2 v = make_float2(0.f, 0.f);
        if (gy >= 0 && gy < Hl && gx >= 0 && gx < Hl)
            v = src[gy*Hl + gx];
        U.t[r][c] = v;
    }
    __syncthreads();

    for (int i = ut; i < 36*32; i += 256) {
        int r = i >> 5, c = i & 31;
        float m1=0.f, m2=0.f, a11=0.f, a22=0.f, cr=0.f;
#pragma unroll
        for (int k = 0; k < 5; k++) {
            float g = c_g[k];
            float2 a = U.t[r][c+k];
            float ga = g*a.x, gq = g*a.y;
            m1 += ga; m2 += gq;
            a11 += ga*a.x; a22 += gq*a.y; cr += ga*a.y;
        }
        U.m12[r][c] = make_float2(m1, m2);
        U.x12[r][c] = make_float2(a11, a22);
        U.a12[r][c] = cr;
    }
    __syncthreads();

    int tx = ut & 31, ty = ut >> 5;
    int y0 = ty*4;
    float2 mu[4], xx[4];
    float cr4[4];
#pragma unroll
    for (int j = 0; j < 4; j++) {
        mu[j] = make_float2(0.f, 0.f);
        xx[j] = make_float2(0.f, 0.f);
        cr4[j] = 0.f;
    }
#pragma unroll
    for (int k = 0; k < 8; k++) {
        float2 m = U.m12[y0+k][tx];
        float2 x = U.x12[y0+k][tx];
        float  a = U.a12[y0+k][tx];
#pragma unroll
        for (int j = 0; j < 4; j++) {
            int tap = k - j;
            if (tap >= 0 && tap < 5) {
                float w = c_g[tap];
                mu[j].x += w*m.x; mu[j].y += w*m.y;
                xx[j].x += w*x.x; xx[j].y += w*x.y;
                cr4[j]  += w*a;
            }
        }
    }
    const float C1 = 1e-4f, C2 = 9e-4f;
#pragma unroll
    for (int j = 0; j < 4; j++) {
        float s1  = xx[j].x - mu[j].x*mu[j].x;
        float s2  = xx[j].y - mu[j].y*mu[j].y;
        float s12 = cr4[j]  - mu[j].x*mu[j].y;
        float den  = s1 + s2 + C2;
        float num2 = 2.f*s12 + C2;
        accC += num2 / den;
        accS += ((2.f*mu[j].x*mu[j].y + C1) * num2) /
                ((mu[j].x*mu[j].x + mu[j].y*mu[j].y + C1) * den);
    }

    if (pool) {
        int rp = ut >> 4, cp = ut & 15;
        int Ho = Hl >> 1;
        float2 q0 = U.t[2*rp+2][2*cp+2], q1 = U.t[2*rp+2][2*cp+3];
        float2 q2 = U.t[2*rp+3][2*cp+2], q3 = U.t[2*rp+3][2*cp+3];
        float2 pv = make_float2(0.25f*(q0.x+q1.x+q2.x+q3.x),
                                0.25f*(q0.y+q1.y+q2.y+q3.y));
        d_L[(size_t)offo + (size_t)b*Ho*Ho + (size_t)((oy>>1)+rp)*Ho + (ox>>1)+cp] = pv;
    }
    __syncthreads();   // protect tile buffers before any next round
}

__device__ __forceinline__ void reduce_unit(Unit& U, float& a, float& c, int ut)
{
    int lane = ut & 31, wid = ut >> 5;
    for (int o = 16; o; o >>= 1) {
        a += __shfl_down_sync(0xffffffffu, a, o);
        c += __shfl_down_sync(0xffffffffu, c, o);
    }
    if (lane == 0) { U.redS[wid] = a; U.redC[wid] = c; }
    __syncthreads();
    if (wid == 0) {
        a = (lane < 8) ? U.redS[lane] : 0.f;
        c = (lane < 8) ? U.redC[lane] : 0.f;
        for (int o = 4; o; o >>= 1) {
            a += __shfl_down_sync(0xffffffffu, a, o);
            c += __shfl_down_sync(0xffffffffu, c, o);
        }
    }
    __syncthreads();
}

// elect: release-fence all threads, one atomicAdd; returns arrival rank.
__device__ __forceinline__ unsigned elect(unsigned* cnt, int tid, unsigned* rank_s)
{
    __threadfence();          // every thread's prior global writes visible
    __syncthreads();
    if (tid == 0) *rank_s = atomicAdd(cnt, 1u);
    __syncthreads();
    return *rank_s;
}

// wait until counter reaches total, then acquire.
__device__ __forceinline__ void wait_all(unsigned* cnt, unsigned total, int tid)
{
    if (tid == 0) {
        while (ld_cg(cnt) < total) __nanosleep(64);
    }
    __syncthreads();
    __threadfence();          // acquire peers' writes
}

// ---------------- the fused kernel -------------------------------------------
__global__ void __launch_bounds__(256)
k_all(const float* __restrict__ pred, const float* __restrict__ tgt,
      float* __restrict__ out)
{
    __shared__ ShMem sm;
    __shared__ unsigned rank_s;
    __shared__ float msarr[8];

    int tid = threadIdx.x;
    int img = blockIdx.x >> 8;
    int sub = blockIdx.x & 255;

    // ================= phase 1: LAB + histogram + L1 (1024 px/block) ========
    {
        for (int i = tid; i < 3*NBINS; i += 256) sm.lab.hist[i] = 0;
        __syncthreads();

        const size_t ibase = (size_t)img*3*NPIX;
        int p = sub*1024 + tid*4;

        float4 pr = *(const float4*)(pred + ibase + p);
        float4 pg = *(const float4*)(pred + ibase + NPIX + p);
        float4 pb = *(const float4*)(pred + ibase + 2*NPIX + p);
        float4 tr = *(const float4*)(tgt  + ibase + p);
        float4 tg = *(const float4*)(tgt  + ibase + NPIX + p);
        float4 tb = *(const float4*)(tgt  + ibase + 2*NPIX + p);

        float* prf = &pr.x; float* pgf = &pg.x; float* pbf = &pb.x;
        float* trf = &tr.x; float* tgf = &tg.x; float* tbf = &tb.x;
        float pls[4], tls[4];
        float l1acc = 0.f;
#pragma unroll
        for (int j = 0; j < 4; j++) {
            float pl, pa, pbc, tl, ta, tbc;
            rgb2lab_norm(prf[j], pgf[j], pbf[j], pl, pa, pbc);
            rgb2lab_norm(trf[j], tgf[j], tbf[j], tl, ta, tbc);
            pls[j] = pl; tls[j] = tl;
            atomicAdd(&sm.lab.hist[0*NBINS + bin_of(pl)],   1);
            atomicAdd(&sm.lab.hist[1*NBINS + bin_of(pa)],   1);
            atomicAdd(&sm.lab.hist[2*NBINS + bin_of(pbc)],  1);
            atomicAdd(&sm.lab.hist[0*NBINS + bin_of(tl)],  -1);
            atomicAdd(&sm.lab.hist[1*NBINS + bin_of(ta)],  -1);
            atomicAdd(&sm.lab.hist[2*NBINS + bin_of(tbc)], -1);
            l1acc += fabsf(pl-tl) + fabsf(pa-ta) + fabsf(pbc-tbc);
        }
        float4* dst = (float4*)&d_L[(size_t)img*NPIX + p];
        dst[0] = make_float4(pls[0], tls[0], pls[1], tls[1]);
        dst[1] = make_float4(pls[2], tls[2], pls[3], tls[3]);
        __syncthreads();

        for (int i = tid; i < 3*NBINS; i += 256) {
            int hd = sm.lab.hist[i];
            if (hd) atomicAdd(&d_histd[img*3*NBINS + i], hd);
        }

        float v = l1acc;
        for (int o = 16; o; o >>= 1) v += __shfl_down_sync(0xffffffffu, v, o);
        int lane = tid & 31, wid = tid >> 5;
        if (lane == 0) sm.lab.red[wid] = v;
        __syncthreads();
        if (wid == 0) {
            v = (lane < 8) ? sm.lab.red[lane] : 0.f;
            for (int o = 4; o; o >>= 1) v += __shfl_down_sync(0xffffffffu, v, o);
            if (lane == 0) atomicAdd(&d_l1sum, v);
        }
    }

    // stage 0: wait for this image's LAB (all 256 blocks); everyone continues
    elect(&g_cnt[img][0], tid, &rank_s);
    wait_all(&g_cnt[img][0], 256u, tid);
    __syncthreads();                      // lab shared -> Unit reuse safe

    // ================= L0: 256 tiles/img, one per block ======================
    {
        float aS = 0.f, aC = 0.f;
        ssim_tile32(sm.u, tid, OFF0, OFF1, 512, img, sub & 15, sub >> 4, true, aS, aC);
        reduce_unit(sm.u, aS, aC, tid);
        if (tid == 0) {
            atomicAdd(&d_ssim_sum[img*5 + 0], aS);
            atomicAdd(&d_cs_sum[img*5 + 0], aC);
        }
        __syncthreads();
    }

    // stage 1: keep last 64 of 256
    {
        unsigned r = elect(&g_cnt[img][1], tid, &rank_s);
        if (r < 192u) return;
        wait_all(&g_cnt[img][1], 256u, tid);
        sub = (int)r - 192;               // 0..63
    }

    // ================= L1: 64 tiles/img ======================================
    {
        float aS = 0.f, aC = 0.f;
        ssim_tile32(sm.u, tid, OFF1, OFF2, 256, img, sub & 7, sub >> 3, true, aS, aC);
        reduce_unit(sm.u, aS, aC, tid);
        if (tid == 0) {
            atomicAdd(&d_ssim_sum[img*5 + 1], aS);
            atomicAdd(&d_cs_sum[img*5 + 1], aC);
        }
        __syncthreads();
    }

    // stage 2: keep last 16 of 64
    {
        unsigned r = elect(&g_cnt[img][2], tid, &rank_s);
        if (r < 48u) return;
        wait_all(&g_cnt[img][2], 64u, tid);
        sub = (int)r - 48;                // 0..15
    }

    // ================= L2: 16 tiles/img ======================================
    {
        float aS = 0.f, aC = 0.f;
        ssim_tile32(sm.u, tid, OFF2, OFF3, 128, img, sub & 3, sub >> 2, true, aS, aC);
        reduce_unit(sm.u, aS, aC, tid);
        if (tid == 0) {
            atomicAdd(&d_ssim_sum[img*5 + 2], aS);
            atomicAdd(&d_cs_sum[img*5 + 2], aC);
        }
        __syncthreads();
    }

    // stage 3: keep last 4 of 16
    {
        unsigned r = elect(&g_cnt[img][3], tid, &rank_s);
        if (r < 12u) return;
        wait_all(&g_cnt[img][3], 16u, tid);
        sub = (int)r - 12;                // 0..3
    }

    // ================= L3: 4 tiles/img =======================================
    {
        float aS = 0.f, aC = 0.f;
        ssim_tile32(sm.u, tid, OFF3, OFF4, 64, img, sub & 1, sub >> 1, true, aS, aC);
        reduce_unit(sm.u, aS, aC, tid);
        if (tid == 0) {
            atomicAdd(&d_ssim_sum[img*5 + 3], aS);
            atomicAdd(&d_cs_sum[img*5 + 3], aC);
        }
        __syncthreads();
    }

    // stage 4: keep last 1 of 4
    {
        unsigned r = elect(&g_cnt[img][4], tid, &rank_s);
        if (r < 3u) return;
        wait_all(&g_cnt[img][4], 4u, tid);
    }

    // ================= L4 (1 tile) + histogram L1 for this image =============
    {
        float aS = 0.f, aC = 0.f;
        ssim_tile32(sm.u, tid, OFF4, 0, 32, img, 0, 0, false, aS, aC);
        reduce_unit(sm.u, aS, aC, tid);
        if (tid == 0) {
            d_ssim_sum[img*5 + 4] = aS;
            d_cs_sum[img*5 + 4]   = aC;
        }
        __syncthreads();

        float s = 0.f;
        for (int i = tid; i < 3*NBINS; i += 256)
            s += fabsf((float)d_histd[img*3*NBINS + i]);
        float dummy = 0.f;
        reduce_unit(sm.u, s, dummy, tid);
        if (tid == 0) d_l1img[img] = s * (1.f/768.f);
        __syncthreads();
    }

    // ================= global elect: last of 8 does final ====================
    {
        unsigned r = elect(&g_final, tid, &rank_s);
        if (r != (unsigned)(Bn - 1)) return;
        __threadfence();                  // acquire other images' results
    }

    if (tid < 8) {
        const float wts[5] = {0.0448f, 0.2856f, 0.3001f, 0.2363f, 0.1333f};
        const float cnt[5] = {262144.f, 65536.f, 16384.f, 4096.f, 1024.f};
        float ms = 1.f;
        for (int l = 0; l < 4; l++) {
            float mcs = d_cs_sum[tid*5 + l] / cnt[l];
            ms *= powf((mcs + 1.f)*0.5f, wts[l]);
        }
        float mss4 = d_ssim_sum[tid*5 + 4] / cnt[4];
        ms *= powf((mss4 + 1.f)*0.5f, wts[4]);
        msarr[tid] = 1.f - ms;
    }
    __syncthreads();

    if (tid == 0) {
        float hist_loss = 0.f;
        for (int i = 0; i < 8; i++)
            hist_loss += exp2f((float)(i - 8)) * (d_l1img[i] + 1.f);
        float scaler = (float)NPIX / 20.f;
        hist_loss = hist_loss / 8.f / scaler;
        float lab_l1 = d_l1sum / (float)(Bn*3*NPIX);
        float sl = 0.f;
        for (int i = 0; i < 8; i++) sl += msarr[i];
        sl *= (1.f/8.f);
        out[0] = lab_l1 + hist_loss;
        out[1] = sl;
    }
    __syncthreads();

    // re-zero ALL state for the next graph replay (this is the last block alive)
    for (int i = tid; i < Bn*3*NBINS; i += 256) d_histd[i] = 0;
    if (tid < Bn*5) { d_ssim_sum[tid] = 0.f; d_cs_sum[tid] = 0.f; }
    if (tid < Bn*5) ((unsigned*)g_cnt)[tid] = 0u;
    if (tid == 0) { d_l1sum = 0.f; g_final = 0u; __threadfence(); }
}

// ---------------- launch ------------------------------------------------------
extern "C" void kernel_launch(void* const* d_in, const int* in_sizes, int n_in,
                              void* d_out, int out_size)
{
    const float* pred = (const float*)d_in[1];
    const float* tgt  = (const float*)d_in[2];
    float* out = (float*)d_out;

    k_all<<<Bn*256, 256>>>(pred, tgt, out);
}

// round 13
// speedup vs baseline: 1.3106x; 1.3106x over previous
#include <cuda_runtime.h>
#include <math.h>

#define Bn    8
#define NPIX  (512*512)
#define NBINS 256

#define OFF0 0u
#define OFF1 2097152u
#define OFF2 2621440u
#define OFF3 2752512u
#define OFF4 2785280u

#define G0 0.12007823f
#define G1 0.23388087f
#define G2 0.29208180f
__device__ __constant__ float c_g[5] = {G0, G1, G2, G1, G0};

// interleaved pyramid: d_L[i] = (pred_L, tgt_L)
__device__ float2 d_L[2793472];
__device__ int    d_histd[Bn*3*NBINS];     // signed: pred minus tgt counts
__device__ float  d_l1sum;
__device__ float  d_ssim_sum[Bn*5];
__device__ float  d_cs_sum[Bn*5];
__device__ float  d_l1img[Bn];
__device__ unsigned g_cnt[Bn][3];
__device__ unsigned g_final;

__device__ __forceinline__ unsigned ld_cg(const unsigned* p)
{
    unsigned v;
    asm volatile("ld.global.cg.u32 %0, [%1];" : "=r"(v) : "l"(p) : "memory");
    return v;
}

// ---------------- RGB -> normalized LAB -------------------------------------
__device__ __forceinline__ float srgb_lin(float x)
{
    if (x <= 0.04045f) return x * (1.f/12.92f);
    float y = (fmaxf(x, 1e-4f) + 0.055f) * (1.f/1.055f);
    return __powf(y, 2.4f);
}

__device__ __forceinline__ float f_lab(float t)
{
    const float e3 = 0.008856451679035631f;
    if (t <= e3) return t * (841.f/108.f) + (4.f/29.f);
    return __powf(fmaxf(t, 1e-4f), 1.f/3.f);
}

__device__ __forceinline__ void rgb2lab_norm(float r, float g, float b,
                                             float& L, float& A, float& Bc)
{
    float lr = srgb_lin(r), lg = srgb_lin(g), lb = srgb_lin(b);
    float X = lr*0.412453f + lg*0.357580f + lb*0.180423f;
    float Y = lr*0.212671f + lg*0.715160f + lb*0.072169f;
    float Z = lr*0.019334f + lg*0.119193f + lb*0.950227f;
    X *= (1.f/0.950456f);
    Z *= (1.f/1.088754f);
    float fx = f_lab(X), fy = f_lab(Y), fz = f_lab(Z);
    float Ll = 116.f*fy - 16.f;
    float Aa = 500.f*(fx - fy);
    float Bb = 200.f*(fy - fz);
    L  = fminf(fmaxf(Ll * 0.01f,                 0.f), 1.f);
    A  = fminf(fmaxf((Aa*(1.f/110.f)+1.f)*0.5f,  0.f), 1.f);
    Bc = fminf(fmaxf((Bb*(1.f/110.f)+1.f)*0.5f,  0.f), 1.f);
}

__device__ __forceinline__ int bin_of(float v)
{
    int b = (int)(v * 256.f);
    return b > 255 ? 255 : b;
}

// ---------------- fused LAB + signed histogram + L1 + L store ---------------
// grid (128, 8) x 256 threads; 8 px/thread
__global__ void k_lab(const float* __restrict__ pred, const float* __restrict__ tgt)
{
    __shared__ int   sh[3*NBINS];
    __shared__ float red[8];
    int b   = blockIdx.y;
    int tid = threadIdx.x;

    for (int i = tid; i < 3*NBINS; i += 256) sh[i] = 0;
    __syncthreads();

    const size_t ibase = (size_t)b*3*NPIX;
    float l1acc = 0.f;

#pragma unroll
    for (int it = 0; it < 2; it++) {
        int p = blockIdx.x*2048 + it*1024 + tid*4;
        float4 pr = *(const float4*)(pred + ibase + p);
        float4 pg = *(const float4*)(pred + ibase + NPIX + p);
        float4 pb = *(const float4*)(pred + ibase + 2*NPIX + p);
        float4 tr = *(const float4*)(tgt  + ibase + p);
        float4 tg = *(const float4*)(tgt  + ibase + NPIX + p);
        float4 tb = *(const float4*)(tgt  + ibase + 2*NPIX + p);

        float* prf = &pr.x; float* pgf = &pg.x; float* pbf = &pb.x;
        float* trf = &tr.x; float* tgf = &tg.x; float* tbf = &tb.x;
        float pls[4], tls[4];
#pragma unroll
        for (int j = 0; j < 4; j++) {
            float pl, pa, pbc, tl, ta, tbc;
            rgb2lab_norm(prf[j], pgf[j], pbf[j], pl, pa, pbc);
            rgb2lab_norm(trf[j], tgf[j], tbf[j], tl, ta, tbc);
            pls[j] = pl; tls[j] = tl;
            atomicAdd(&sh[0*NBINS + bin_of(pl)],   1);
            atomicAdd(&sh[1*NBINS + bin_of(pa)],   1);
            atomicAdd(&sh[2*NBINS + bin_of(pbc)],  1);
            atomicAdd(&sh[0*NBINS + bin_of(tl)],  -1);
            atomicAdd(&sh[1*NBINS + bin_of(ta)],  -1);
            atomicAdd(&sh[2*NBINS + bin_of(tbc)], -1);
            l1acc += fabsf(pl-tl) + fabsf(pa-ta) + fabsf(pbc-tbc);
        }
        float4* dst = (float4*)&d_L[(size_t)b*NPIX + p];
        dst[0] = make_float4(pls[0], tls[0], pls[1], tls[1]);
        dst[1] = make_float4(pls[2], tls[2], pls[3], tls[3]);
    }
    __syncthreads();

    for (int i = tid; i < 3*NBINS; i += 256) {
        int hd = sh[i];
        if (hd) atomicAdd(&d_histd[b*3*NBINS + i], hd);
    }

    float v = l1acc;
    for (int o = 16; o; o >>= 1) v += __shfl_down_sync(0xffffffffu, v, o);
    int lane = tid & 31, wid = tid >> 5;
    if (lane == 0) red[wid] = v;
    __syncthreads();
    if (wid == 0) {
        v = (lane < 8) ? red[lane] : 0.f;
        for (int o = 4; o; o >>= 1) v += __shfl_down_sync(0xffffffffu, v, o);
        if (lane == 0) atomicAdd(&d_l1sum, v);
    }
}

// ---------------- 32x32 SSIM tile (256 threads, block == unit) --------------
struct Unit {
    float2 t[36][36];
    float2 m12[36][32];
    float2 x12[36][32];
    float  a12[36][32];
    float  redS[8], redC[8];
};

__device__ __forceinline__ void ssim_tile32(Unit& U, int ut,
                                            unsigned off, unsigned offo,
                                            int Hl, int b, int tix, int tiy,
                                            bool pool, float& accS, float& accC)
{
    const float2* src = d_L + off + (size_t)b*Hl*Hl;
    int ox = tix*32, oy = tiy*32;

    for (int i = ut; i < 36*36; i += 256) {
        int r = i/36, c = i%36;
        int gy = oy + r - 2, gx = ox + c - 2;
        float2 v = make_float2(0.f, 0.f);
        if (gy >= 0 && gy < Hl && gx >= 0 && gx < Hl)
            v = src[gy*Hl + gx];
        U.t[r][c] = v;
    }
    __syncthreads();

    for (int i = ut; i < 36*32; i += 256) {
        int r = i >> 5, c = i & 31;
        float m1=0.f, m2=0.f, a11=0.f, a22=0.f, cr=0.f;
#pragma unroll
        for (int k = 0; k < 5; k++) {
            float g = c_g[k];
            float2 a = U.t[r][c+k];
            float ga = g*a.x, gq = g*a.y;
            m1 += ga; m2 += gq;
            a11 += ga*a.x; a22 += gq*a.y; cr += ga*a.y;
        }
        U.m12[r][c] = make_float2(m1, m2);
        U.x12[r][c] = make_float2(a11, a22);
        U.a12[r][c] = cr;
    }
    __syncthreads();

    int tx = ut & 31, ty = ut >> 5;
    int y0 = ty*4;
    float2 mu[4], xx[4];
    float cr4[4];
#pragma unroll
    for (int j = 0; j < 4; j++) {
        mu[j] = make_float2(0.f, 0.f);
        xx[j] = make_float2(0.f, 0.f);
        cr4[j] = 0.f;
    }
#pragma unroll
    for (int k = 0; k < 8; k++) {
        float2 m = U.m12[y0+k][tx];
        float2 x = U.x12[y0+k][tx];
        float  a = U.a12[y0+k][tx];
#pragma unroll
        for (int j = 0; j < 4; j++) {
            int tap = k - j;
            if (tap >= 0 && tap < 5) {
                float w = c_g[tap];
                mu[j].x += w*m.x; mu[j].y += w*m.y;
                xx[j].x += w*x.x; xx[j].y += w*x.y;
                cr4[j]  += w*a;
            }
        }
    }
    const float C1 = 1e-4f, C2 = 9e-4f;
#pragma unroll
    for (int j = 0; j < 4; j++) {
        float s1  = xx[j].x - mu[j].x*mu[j].x;
        float s2  = xx[j].y - mu[j].y*mu[j].y;
        float s12 = cr4[j]  - mu[j].x*mu[j].y;
        float den  = s1 + s2 + C2;
        float num2 = 2.f*s12 + C2;
        accC += num2 / den;
        accS += ((2.f*mu[j].x*mu[j].y + C1) * num2) /
                ((mu[j].x*mu[j].x + mu[j].y*mu[j].y + C1) * den);
    }

    if (pool) {
        int rp = ut >> 4, cp = ut & 15;
        int Ho = Hl >> 1;
        float2 q0 = U.t[2*rp+2][2*cp+2], q1 = U.t[2*rp+2][2*cp+3];
        float2 q2 = U.t[2*rp+3][2*cp+2], q3 = U.t[2*rp+3][2*cp+3];
        float2 pv = make_float2(0.25f*(q0.x+q1.x+q2.x+q3.x),
                                0.25f*(q0.y+q1.y+q2.y+q3.y));
        d_L[(size_t)offo + (size_t)b*Ho*Ho + (size_t)((oy>>1)+rp)*Ho + (ox>>1)+cp] = pv;
    }
    __syncthreads();
}

__device__ __forceinline__ void reduce_unit(Unit& U, float& a, float& c, int ut)
{
    int lane = ut & 31, wid = ut >> 5;
    for (int o = 16; o; o >>= 1) {
        a += __shfl_down_sync(0xffffffffu, a, o);
        c += __shfl_down_sync(0xffffffffu, c, o);
    }
    if (lane == 0) { U.redS[wid] = a; U.redC[wid] = c; }
    __syncthreads();
    if (wid == 0) {
        a = (lane < 8) ? U.redS[lane] : 0.f;
        c = (lane < 8) ? U.redC[lane] : 0.f;
        for (int o = 4; o; o >>= 1) {
            a += __shfl_down_sync(0xffffffffu, a, o);
            c += __shfl_down_sync(0xffffffffu, c, o);
        }
    }
    __syncthreads();
}

// elect: release-fence all threads, one atomicAdd; returns arrival rank.
__device__ __forceinline__ unsigned elect(unsigned* cnt, int tid, unsigned* rank_s)
{
    __threadfence();
    __syncthreads();
    if (tid == 0) *rank_s = atomicAdd(cnt, 1u);
    __syncthreads();
    return *rank_s;
}

__device__ __forceinline__ void wait_all(unsigned* cnt, unsigned total, int tid)
{
    if (tid == 0) {
        while (ld_cg(cnt) < total) __nanosleep(64);
    }
    __syncthreads();
    __threadfence();
}

// ---------------- standalone SSIM kernel for L0 -----------------------------
__global__ void __launch_bounds__(256)
k_ssim0()
{
    __shared__ Unit U;
    int b  = blockIdx.z;
    int ut = threadIdx.x;

    float aS = 0.f, aC = 0.f;
    ssim_tile32(U, ut, OFF0, OFF1, 512, b, blockIdx.x, blockIdx.y, true, aS, aC);
    reduce_unit(U, aS, aC, ut);
    if (ut == 0) {
        atomicAdd(&d_ssim_sum[b*5 + 0], aS);
        atomicAdd(&d_cs_sum[b*5 + 0], aC);
    }
}

// ---------------- k_rest: L1..L4 + hist + final cascade; 512 blocks ---------
// All 512 blocks resident (<=64 regs via launch_bounds, 34KB smem -> >=4/SM).
__global__ void __launch_bounds__(256, 4)
k_rest(float* __restrict__ out)
{
    __shared__ Unit U;
    __shared__ unsigned rank_s;
    __shared__ float msarr[8];

    int tid = threadIdx.x;
    int img = blockIdx.x >> 6;
    int sub = blockIdx.x & 63;

    // ================= L1: 64 tiles/img, 1 round =============================
    {
        float aS = 0.f, aC = 0.f;
        ssim_tile32(U, tid, OFF1, OFF2, 256, img, sub & 7, sub >> 3, true, aS, aC);
        reduce_unit(U, aS, aC, tid);
        if (tid == 0) {
            atomicAdd(&d_ssim_sum[img*5 + 1], aS);
            atomicAdd(&d_cs_sum[img*5 + 1], aC);
        }
        __syncthreads();
    }

    // keep last 16 of 64
    {
        unsigned r = elect(&g_cnt[img][0], tid, &rank_s);
        if (r < 48u) return;
        wait_all(&g_cnt[img][0], 64u, tid);
        sub = (int)r - 48;                // 0..15
    }

    // ================= L2: 16 tiles/img =======================================
    {
        float aS = 0.f, aC = 0.f;
        ssim_tile32(U, tid, OFF2, OFF3, 128, img, sub & 3, sub >> 2, true, aS, aC);
        reduce_unit(U, aS, aC, tid);
        if (tid == 0) {
            atomicAdd(&d_ssim_sum[img*5 + 2], aS);
            atomicAdd(&d_cs_sum[img*5 + 2], aC);
        }
        __syncthreads();
    }

    // keep last 4 of 16
    {
        unsigned r = elect(&g_cnt[img][1], tid, &rank_s);
        if (r < 12u) return;
        wait_all(&g_cnt[img][1], 16u, tid);
        sub = (int)r - 12;                // 0..3
    }

    // ================= L3: 4 tiles/img ========================================
    {
        float aS = 0.f, aC = 0.f;
        ssim_tile32(U, tid, OFF3, OFF4, 64, img, sub & 1, sub >> 1, true, aS, aC);
        reduce_unit(U, aS, aC, tid);
        if (tid == 0) {
            atomicAdd(&d_ssim_sum[img*5 + 3], aS);
            atomicAdd(&d_cs_sum[img*5 + 3], aC);
        }
        __syncthreads();
    }

    // keep last 1 of 4
    {
        unsigned r = elect(&g_cnt[img][2], tid, &rank_s);
        if (r < 3u) return;
        wait_all(&g_cnt[img][2], 4u, tid);
    }

    // ================= L4 (1 tile) + histogram L1 =============================
    {
        float aS = 0.f, aC = 0.f;
        ssim_tile32(U, tid, OFF4, 0, 32, img, 0, 0, false, aS, aC);
        reduce_unit(U, aS, aC, tid);
        if (tid == 0) {
            d_ssim_sum[img*5 + 4] = aS;
            d_cs_sum[img*5 + 4]   = aC;
        }
        __syncthreads();

        float s = 0.f;
        for (int i = tid; i < 3*NBINS; i += 256)
            s += fabsf((float)d_histd[img*3*NBINS + i]);
        float dummy = 0.f;
        reduce_unit(U, s, dummy, tid);
        if (tid == 0) d_l1img[img] = s * (1.f/768.f);
        __syncthreads();
    }

    // ================= global elect: last of 8 does final =====================
    {
        unsigned r = elect(&g_final, tid, &rank_s);
        if (r != (unsigned)(Bn - 1)) return;
        __threadfence();
    }

    if (tid < 8) {
        const float wts[5] = {0.0448f, 0.2856f, 0.3001f, 0.2363f, 0.1333f};
        const float cnt[5] = {262144.f, 65536.f, 16384.f, 4096.f, 1024.f};
        float ms = 1.f;
        for (int l = 0; l < 4; l++) {
            float mcs = d_cs_sum[tid*5 + l] / cnt[l];
            ms *= powf((mcs + 1.f)*0.5f, wts[l]);
        }
        float mss4 = d_ssim_sum[tid*5 + 4] / cnt[4];
        ms *= powf((mss4 + 1.f)*0.5f, wts[4]);
        msarr[tid] = 1.f - ms;
    }
    __syncthreads();

    if (tid == 0) {
        float hist_loss = 0.f;
        for (int i = 0; i < 8; i++)
            hist_loss += exp2f((float)(i - 8)) * (d_l1img[i] + 1.f);
        float scaler = (float)NPIX / 20.f;
        hist_loss = hist_loss / 8.f / scaler;
        float lab_l1 = d_l1sum / (float)(Bn*3*NPIX);
        float sl = 0.f;
        for (int i = 0; i < 8; i++) sl += msarr[i];
        sl *= (1.f/8.f);
        out[0] = lab_l1 + hist_loss;
        out[1] = sl;
    }
    __syncthreads();

    // re-zero ALL state for next graph replay (last block alive)
    for (int i = tid; i < Bn*3*NBINS; i += 256) d_histd[i] = 0;
    if (tid < Bn*5) { d_ssim_sum[tid] = 0.f; d_cs_sum[tid] = 0.f; }
    if (tid < Bn*3) ((unsigned*)g_cnt)[tid] = 0u;
    if (tid == 0) { d_l1sum = 0.f; g_final = 0u; __threadfence(); }
}

// ---------------- launch ------------------------------------------------------
extern "C" void kernel_launch(void* const* d_in, const int* in_sizes, int n_in,
                              void* d_out, int out_size)
{
    const float* pred = (const float*)d_in[1];
    const float* tgt  = (const float*)d_in[2];
    float* out = (float*)d_out;

    dim3 g1(128, Bn);
    k_lab<<<g1, 256>>>(pred, tgt);

    k_ssim0<<<dim3(16, 16, Bn), 256>>>();

    k_rest<<<512, 256>>>(out);
}

// round 14
// speedup vs baseline: 1.3836x; 1.0557x over previous
#include <cuda_runtime.h>
#include <math.h>

#define Bn    8
#define NPIX  (512*512)
#define NBINS 256

#define OFF0 0u
#define OFF1 2097152u
#define OFF2 2621440u
#define OFF3 2752512u
#define OFF4 2785280u

#define G0 0.12007823f
#define G1 0.23388087f
#define G2 0.29208180f
__device__ __constant__ float c_g[5] = {G0, G1, G2, G1, G0};

// interleaved pyramid: d_L[i] = (pred_L, tgt_L)
__device__ float2 d_L[2793472];
__device__ int    d_histd[Bn*3*NBINS];     // signed: pred minus tgt counts
__device__ float  d_l1sum;
__device__ float  d_ssim_sum[Bn*5];
__device__ float  d_cs_sum[Bn*5];
__device__ float  d_l1img[Bn];
__device__ unsigned g_final;

__device__ __forceinline__ void bar_sync(int id)
{
    asm volatile("bar.sync %0, 256;" :: "r"(id) : "memory");
}

// ---------------- RGB -> normalized LAB -------------------------------------
__device__ __forceinline__ float srgb_lin(float x)
{
    if (x <= 0.04045f) return x * (1.f/12.92f);
    float y = (fmaxf(x, 1e-4f) + 0.055f) * (1.f/1.055f);
    return __powf(y, 2.4f);
}

__device__ __forceinline__ float f_lab(float t)
{
    const float e3 = 0.008856451679035631f;
    if (t <= e3) return t * (841.f/108.f) + (4.f/29.f);
    return __powf(fmaxf(t, 1e-4f), 1.f/3.f);
}

__device__ __forceinline__ void rgb2lab_norm(float r, float g, float b,
                                             float& L, float& A, float& Bc)
{
    float lr = srgb_lin(r), lg = srgb_lin(g), lb = srgb_lin(b);
    float X = lr*0.412453f + lg*0.357580f + lb*0.180423f;
    float Y = lr*0.212671f + lg*0.715160f + lb*0.072169f;
    float Z = lr*0.019334f + lg*0.119193f + lb*0.950227f;
    X *= (1.f/0.950456f);
    Z *= (1.f/1.088754f);
    float fx = f_lab(X), fy = f_lab(Y), fz = f_lab(Z);
    float Ll = 116.f*fy - 16.f;
    float Aa = 500.f*(fx - fy);
    float Bb = 200.f*(fy - fz);
    L  = __saturatef(Ll * 0.01f);
    A  = __saturatef(Aa*(1.f/220.f) + 0.5f);
    Bc = __saturatef(Bb*(1.f/220.f) + 0.5f);
}

__device__ __forceinline__ int bin_of(float v)
{
    int b = (int)(v * 256.f);
    return b > 255 ? 255 : b;
}

// ---------------- fused LAB + signed histogram + L1 + L store ---------------
// grid (64, 8) x 256 threads; 16 px/thread (4 float4 iters)
__global__ void k_lab(const float* __restrict__ pred, const float* __restrict__ tgt)
{
    __shared__ int   sh[3*NBINS];
    __shared__ float red[8];
    int b   = blockIdx.y;
    int tid = threadIdx.x;

    for (int i = tid; i < 3*NBINS; i += 256) sh[i] = 0;
    __syncthreads();

    int* h0 = &sh[0];
    int* h1 = &sh[NBINS];
    int* h2 = &sh[2*NBINS];

    const size_t ibase = (size_t)b*3*NPIX;
    float l1acc = 0.f;

#pragma unroll
    for (int it = 0; it < 4; it++) {
        int p = blockIdx.x*4096 + it*1024 + tid*4;
        float4 pr = *(const float4*)(pred + ibase + p);
        float4 pg = *(const float4*)(pred + ibase + NPIX + p);
        float4 pb = *(const float4*)(pred + ibase + 2*NPIX + p);
        float4 tr = *(const float4*)(tgt  + ibase + p);
        float4 tg = *(const float4*)(tgt  + ibase + NPIX + p);
        float4 tb = *(const float4*)(tgt  + ibase + 2*NPIX + p);

        float* prf = &pr.x; float* pgf = &pg.x; float* pbf = &pb.x;
        float* trf = &tr.x; float* tgf = &tg.x; float* tbf = &tb.x;
        float pls[4], tls[4];
#pragma unroll
        for (int j = 0; j < 4; j++) {
            float pl, pa, pbc, tl, ta, tbc;
            rgb2lab_norm(prf[j], pgf[j], pbf[j], pl, pa, pbc);
            rgb2lab_norm(trf[j], tgf[j], tbf[j], tl, ta, tbc);
            pls[j] = pl; tls[j] = tl;
            atomicAdd(&h0[bin_of(pl)],   1);
            atomicAdd(&h1[bin_of(pa)],   1);
            atomicAdd(&h2[bin_of(pbc)],  1);
            atomicAdd(&h0[bin_of(tl)],  -1);
            atomicAdd(&h1[bin_of(ta)],  -1);
            atomicAdd(&h2[bin_of(tbc)], -1);
            l1acc += fabsf(pl-tl) + fabsf(pa-ta) + fabsf(pbc-tbc);
        }
        float4* dst = (float4*)&d_L[(size_t)b*NPIX + p];
        dst[0] = make_float4(pls[0], tls[0], pls[1], tls[1]);
        dst[1] = make_float4(pls[2], tls[2], pls[3], tls[3]);
    }
    __syncthreads();

    for (int i = tid; i < 3*NBINS; i += 256) {
        int hd = sh[i];
        if (hd) atomicAdd(&d_histd[b*3*NBINS + i], hd);
    }

    float v = l1acc;
    for (int o = 16; o; o >>= 1) v += __shfl_down_sync(0xffffffffu, v, o);
    int lane = tid & 31, wid = tid >> 5;
    if (lane == 0) red[wid] = v;
    __syncthreads();
    if (wid == 0) {
        v = (lane < 8) ? red[lane] : 0.f;
        for (int o = 4; o; o >>= 1) v += __shfl_down_sync(0xffffffffu, v, o);
        if (lane == 0) atomicAdd(&d_l1sum, v);
    }
}

// ---------------- 32x32 SSIM tile (one 256-thread unit) ---------------------
struct Unit {
    float2 t[36][36];
    float2 m12[36][32];
    float2 x12[36][32];
    float  a12[36][32];
    float  redS[8], redC[8];
};

// syncs with named barrier `bar` (256 threads of the unit only)
__device__ __forceinline__ void ssim_tile32(Unit& U, int ut, int bar,
                                            unsigned off, unsigned offo,
                                            int Hl, int b, int tix, int tiy,
                                            bool pool, float& accS, float& accC)
{
    const float2* src = d_L + off + (size_t)b*Hl*Hl;
    int ox = tix*32, oy = tiy*32;

    for (int i = ut; i < 36*36; i += 256) {
        int r = i/36, c = i%36;
        int gy = oy + r - 2, gx = ox + c - 2;
        float2 v = make_float2(0.f, 0.f);
        if (gy >= 0 && gy < Hl && gx >= 0 && gx < Hl)
            v = src[gy*Hl + gx];
        U.t[r][c] = v;
    }
    bar_sync(bar);

    for (int i = ut; i < 36*32; i += 256) {
        int r = i >> 5, c = i & 31;
        float m1=0.f, m2=0.f, a11=0.f, a22=0.f, cr=0.f;
#pragma unroll
        for (int k = 0; k < 5; k++) {
            float g = c_g[k];
            float2 a = U.t[r][c+k];
            float ga = g*a.x, gq = g*a.y;
            m1 += ga; m2 += gq;
            a11 += ga*a.x; a22 += gq*a.y; cr += ga*a.y;
        }
        U.m12[r][c] = make_float2(m1, m2);
        U.x12[r][c] = make_float2(a11, a22);
        U.a12[r][c] = cr;
    }
    bar_sync(bar);

    int tx = ut & 31, ty = ut >> 5;
    int y0 = ty*4;
    float2 mu[4], xx[4];
    float cr4[4];
#pragma unroll
    for (int j = 0; j < 4; j++) {
        mu[j] = make_float2(0.f, 0.f);
        xx[j] = make_float2(0.f, 0.f);
        cr4[j] = 0.f;
    }
#pragma unroll
    for (int k = 0; k < 8; k++) {
        float2 m = U.m12[y0+k][tx];
        float2 x = U.x12[y0+k][tx];
        float  a = U.a12[y0+k][tx];
#pragma unroll
        for (int j = 0; j < 4; j++) {
            int tap = k - j;
            if (tap >= 0 && tap < 5) {
                float w = c_g[tap];
                mu[j].x += w*m.x; mu[j].y += w*m.y;
                xx[j].x += w*x.x; xx[j].y += w*x.y;
                cr4[j]  += w*a;
            }
        }
    }
    const float C1 = 1e-4f, C2 = 9e-4f;
#pragma unroll
    for (int j = 0; j < 4; j++) {
        float s1  = xx[j].x - mu[j].x*mu[j].x;
        float s2  = xx[j].y - mu[j].y*mu[j].y;
        float s12 = cr4[j]  - mu[j].x*mu[j].y;
        float den  = s1 + s2 + C2;
        float num2 = 2.f*s12 + C2;
        accC += num2 / den;
        accS += ((2.f*mu[j].x*mu[j].y + C1) * num2) /
                ((mu[j].x*mu[j].x + mu[j].y*mu[j].y + C1) * den);
    }

    if (pool) {
        int rp = ut >> 4, cp = ut & 15;
        int Ho = Hl >> 1;
        float2 q0 = U.t[2*rp+2][2*cp+2], q1 = U.t[2*rp+2][2*cp+3];
        float2 q2 = U.t[2*rp+3][2*cp+2], q3 = U.t[2*rp+3][2*cp+3];
        float2 pv = make_float2(0.25f*(q0.x+q1.x+q2.x+q3.x),
                                0.25f*(q0.y+q1.y+q2.y+q3.y));
        d_L[(size_t)offo + (size_t)b*Ho*Ho + (size_t)((oy>>1)+rp)*Ho + (ox>>1)+cp] = pv;
    }
    bar_sync(bar);
}

__device__ __forceinline__ void reduce_unit(Unit& U, float& a, float& c,
                                            int ut, int bar)
{
    int lane = ut & 31, wid = ut >> 5;
    for (int o = 16; o; o >>= 1) {
        a += __shfl_down_sync(0xffffffffu, a, o);
        c += __shfl_down_sync(0xffffffffu, c, o);
    }
    if (lane == 0) { U.redS[wid] = a; U.redC[wid] = c; }
    bar_sync(bar);
    if (wid == 0) {
        a = (lane < 8) ? U.redS[lane] : 0.f;
        c = (lane < 8) ? U.redC[lane] : 0.f;
        for (int o = 4; o; o >>= 1) {
            a += __shfl_down_sync(0xffffffffu, a, o);
            c += __shfl_down_sync(0xffffffffu, c, o);
        }
    }
    bar_sync(bar);
}

// ---------------- batched SSIM level kernel (L0, L1, L2) --------------------
__global__ void __launch_bounds__(256)
k_ssim(unsigned off, unsigned offo, int Hl, int lvl)
{
    __shared__ Unit U;
    int b  = blockIdx.z;
    int ut = threadIdx.x;

    float aS = 0.f, aC = 0.f;
    ssim_tile32(U, ut, 1, off, offo, Hl, b, blockIdx.x, blockIdx.y, true, aS, aC);
    reduce_unit(U, aS, aC, ut, 1);
    if (ut == 0) {
        atomicAdd(&d_ssim_sum[b*5 + lvl], aS);
        atomicAdd(&d_cs_sum[b*5 + lvl], aC);
    }
}

// ---------------- tail: L3 (4 units, 1 round) + L4 + hist; 8 blocks ---------
__global__ void __launch_bounds__(1024, 1)
k_tail8()
{
    extern __shared__ Unit Us[];      // 4 units
    __shared__ float hred[32];

    int tid  = threadIdx.x;
    int ublk = tid >> 8;
    int ut   = tid & 255;
    int b    = blockIdx.x;
    Unit& U  = Us[ublk];
    int bar  = 1 + ublk;              // bar 0 reserved for __syncthreads

    // -------- L3: 4 tiles (64x64), one per unit, single round ---------------
    {
        float aS = 0.f, aC = 0.f;
        ssim_tile32(U, ut, bar, OFF3, OFF4, 64, b, ublk & 1, ublk >> 1, true, aS, aC);
        reduce_unit(U, aS, aC, ut, bar);
        if (ut == 0) {
            atomicAdd(&d_ssim_sum[b*5 + 3], aS);
            atomicAdd(&d_cs_sum[b*5 + 3], aC);
        }
    }
    __syncthreads();                  // all units' L4 pool writes visible

    // -------- L4: 1 tile (whole 32x32 level), unit 0 only --------------------
    if (ublk == 0) {
        float aS = 0.f, aC = 0.f;
        ssim_tile32(U, ut, bar, OFF4, 0, 32, b, 0, 0, false, aS, aC);
        reduce_unit(U, aS, aC, ut, bar);
        if (ut == 0) {
            d_ssim_sum[b*5 + 4] = aS;
            d_cs_sum[b*5 + 4]   = aC;
        }
    }

    // -------- histogram L1 for this image (all 1024 threads) -----------------
    {
        float s = (tid < 3*NBINS) ? fabsf((float)d_histd[b*3*NBINS + tid]) : 0.f;
        int lane = tid & 31, wid = tid >> 5;
        for (int o = 16; o; o >>= 1) s += __shfl_down_sync(0xffffffffu, s, o);
        if (lane == 0) hred[wid] = s;
        __syncthreads();
        if (wid == 0) {
            s = hred[lane];
            for (int o = 16; o; o >>= 1) s += __shfl_down_sync(0xffffffffu, s, o);
            if (lane == 0) d_l1img[b] = s * (1.f/768.f);
        }
    }
}

// ---------------- final assembly + state re-zero (1 block) ------------------
__global__ void __launch_bounds__(256)
k_final(float* __restrict__ out)
{
    __shared__ float msarr[8];
    int ut = threadIdx.x;

    if (ut < 8) {
        const float wts[5] = {0.0448f, 0.2856f, 0.3001f, 0.2363f, 0.1333f};
        const float cnt[5] = {262144.f, 65536.f, 16384.f, 4096.f, 1024.f};
        float ms = 1.f;
        for (int l = 0; l < 4; l++) {
            float mcs = d_cs_sum[ut*5 + l] / cnt[l];
            ms *= powf((mcs + 1.f)*0.5f, wts[l]);
        }
        float mss4 = d_ssim_sum[ut*5 + 4] / cnt[4];
        ms *= powf((mss4 + 1.f)*0.5f, wts[4]);
        msarr[ut] = 1.f - ms;
    }
    __syncthreads();

    if (ut == 0) {
        float hist_loss = 0.f;
        for (int i = 0; i < 8; i++)
            hist_loss += exp2f((float)(i - 8)) * (d_l1img[i] + 1.f);
        float scaler = (float)NPIX / 20.f;
        hist_loss = hist_loss / 8.f / scaler;
        float lab_l1 = d_l1sum / (float)(Bn*3*NPIX);
        float sl = 0.f;
        for (int i = 0; i < 8; i++) sl += msarr[i];
        sl *= (1.f/8.f);
        out[0] = lab_l1 + hist_loss;
        out[1] = sl;
    }

    // re-zero accumulators for next graph replay
    for (int i = ut; i < Bn*3*NBINS; i += 256) d_histd[i] = 0;
    if (ut < Bn*5) { d_ssim_sum[ut] = 0.f; d_cs_sum[ut] = 0.f; }
    if (ut == 0) d_l1sum = 0.f;
}

// ---------------- launch ------------------------------------------------------
extern "C" void kernel_launch(void* const* d_in, const int* in_sizes, int n_in,
                              void* d_out, int out_size)
{
    const float* pred = (const float*)d_in[1];
    const float* tgt  = (const float*)d_in[2];
    float* out = (float*)d_out;

    static int smem_set = 0;
    const int tail_smem = (int)(4*sizeof(Unit));
    if (!smem_set) {
        cudaFuncSetAttribute(k_tail8, cudaFuncAttributeMaxDynamicSharedMemorySize,
                             tail_smem);
        smem_set = 1;
    }

    dim3 g1(64, Bn);
    k_lab<<<g1, 256>>>(pred, tgt);

    k_ssim<<<dim3(16, 16, Bn), 256>>>(OFF0, OFF1, 512, 0);
    k_ssim<<<dim3(8, 8, Bn),   256>>>(OFF1, OFF2, 256, 1);
    k_ssim<<<dim3(4, 4, Bn),   256>>>(OFF2, OFF3, 128, 2);

    k_tail8<<<Bn, 1024, tail_smem>>>();
    k_final<<<1, 256>>>(out);
}

// round 15
// speedup vs baseline: 1.5958x; 1.1534x over previous
#include <cuda_runtime.h>
#include <math.h>

#define Bn    8
#define NPIX  (512*512)
#define NBINS 256

#define OFF0 0u
#define OFF1 2097152u
#define OFF2 2621440u
#define OFF3 2752512u
#define OFF4 2785280u

#define G0 0.12007823f
#define G1 0.23388087f
#define G2 0.29208180f
__device__ __constant__ float c_g[5] = {G0, G1, G2, G1, G0};

// interleaved pyramid: d_L[i] = (pred_L, tgt_L)
__device__ float2 d_L[2793472];
__device__ int    d_histd[Bn*3*NBINS];     // signed: pred minus tgt counts
__device__ float  d_l1sum;
__device__ float  d_ssim_sum[Bn*5];
__device__ float  d_cs_sum[Bn*5];

__device__ __forceinline__ void bar_sync(int id)
{
    asm volatile("bar.sync %0, 256;" :: "r"(id) : "memory");
}

// ---------------- RGB -> normalized LAB -------------------------------------
__device__ __forceinline__ float srgb_lin(float x)
{
    if (x <= 0.04045f) return x * (1.f/12.92f);
    float y = (fmaxf(x, 1e-4f) + 0.055f) * (1.f/1.055f);
    return __powf(y, 2.4f);
}

__device__ __forceinline__ float f_lab(float t)
{
    const float e3 = 0.008856451679035631f;
    if (t <= e3) return t * (841.f/108.f) + (4.f/29.f);
    return __powf(fmaxf(t, 1e-4f), 1.f/3.f);
}

__device__ __forceinline__ void rgb2lab_norm(float r, float g, float b,
                                             float& L, float& A, float& Bc)
{
    float lr = srgb_lin(r), lg = srgb_lin(g), lb = srgb_lin(b);
    float X = lr*0.412453f + lg*0.357580f + lb*0.180423f;
    float Y = lr*0.212671f + lg*0.715160f + lb*0.072169f;
    float Z = lr*0.019334f + lg*0.119193f + lb*0.950227f;
    X *= (1.f/0.950456f);
    Z *= (1.f/1.088754f);
    float fx = f_lab(X), fy = f_lab(Y), fz = f_lab(Z);
    float Ll = 116.f*fy - 16.f;
    float Aa = 500.f*(fx - fy);
    float Bb = 200.f*(fy - fz);
    L  = __saturatef(Ll * 0.01f);
    A  = __saturatef(Aa*(1.f/220.f) + 0.5f);
    Bc = __saturatef(Bb*(1.f/220.f) + 0.5f);
}

__device__ __forceinline__ int bin_of(float v)
{
    int b = (int)(v * 256.f);
    return b > 255 ? 255 : b;
}

// ---------------- fused LAB + signed histogram + L1 + L store ---------------
// grid (128, 8) x 256 threads; 8 px/thread
__global__ void k_lab(const float* __restrict__ pred, const float* __restrict__ tgt)
{
    __shared__ int   sh[3*NBINS];
    __shared__ float red[8];
    int b   = blockIdx.y;
    int tid = threadIdx.x;

    for (int i = tid; i < 3*NBINS; i += 256) sh[i] = 0;
    __syncthreads();

    int* h0 = &sh[0];
    int* h1 = &sh[NBINS];
    int* h2 = &sh[2*NBINS];

    const size_t ibase = (size_t)b*3*NPIX;
    float l1acc = 0.f;

#pragma unroll
    for (int it = 0; it < 2; it++) {
        int p = blockIdx.x*2048 + it*1024 + tid*4;
        float4 pr = *(const float4*)(pred + ibase + p);
        float4 pg = *(const float4*)(pred + ibase + NPIX + p);
        float4 pb = *(const float4*)(pred + ibase + 2*NPIX + p);
        float4 tr = *(const float4*)(tgt  + ibase + p);
        float4 tg = *(const float4*)(tgt  + ibase + NPIX + p);
        float4 tb = *(const float4*)(tgt  + ibase + 2*NPIX + p);

        float* prf = &pr.x; float* pgf = &pg.x; float* pbf = &pb.x;
        float* trf = &tr.x; float* tgf = &tg.x; float* tbf = &tb.x;
        float pls[4], tls[4];
#pragma unroll
        for (int j = 0; j < 4; j++) {
            float pl, pa, pbc, tl, ta, tbc;
            rgb2lab_norm(prf[j], pgf[j], pbf[j], pl, pa, pbc);
            rgb2lab_norm(trf[j], tgf[j], tbf[j], tl, ta, tbc);
            pls[j] = pl; tls[j] = tl;
            atomicAdd(&h0[bin_of(pl)],   1);
            atomicAdd(&h1[bin_of(pa)],   1);
            atomicAdd(&h2[bin_of(pbc)],  1);
            atomicAdd(&h0[bin_of(tl)],  -1);
            atomicAdd(&h1[bin_of(ta)],  -1);
            atomicAdd(&h2[bin_of(tbc)], -1);
            l1acc += fabsf(pl-tl) + fabsf(pa-ta) + fabsf(pbc-tbc);
        }
        float4* dst = (float4*)&d_L[(size_t)b*NPIX + p];
        dst[0] = make_float4(pls[0], tls[0], pls[1], tls[1]);
        dst[1] = make_float4(pls[2], tls[2], pls[3], tls[3]);
    }
    __syncthreads();

    for (int i = tid; i < 3*NBINS; i += 256) {
        int hd = sh[i];
        if (hd) atomicAdd(&d_histd[b*3*NBINS + i], hd);
    }

    float v = l1acc;
    for (int o = 16; o; o >>= 1) v += __shfl_down_sync(0xffffffffu, v, o);
    int lane = tid & 31, wid = tid >> 5;
    if (lane == 0) red[wid] = v;
    __syncthreads();
    if (wid == 0) {
        v = (lane < 8) ? red[lane] : 0.f;
        for (int o = 4; o; o >>= 1) v += __shfl_down_sync(0xffffffffu, v, o);
        if (lane == 0) atomicAdd(&d_l1sum, v);
    }
}

// ---------------- 32x32 SSIM tile core (256 threads) ------------------------
struct Unit {
    float2 t[36][36];
    float2 m12[36][32];
    float2 x12[36][32];
    float  a12[36][32];
    float  redS[8], redC[8];
};

// SSIM moments + per-thread 4-output accumulation. No pooling.
__device__ __forceinline__ void ssim_core(Unit& U, int ut,
                                          unsigned off, int Hl, int b,
                                          int tix, int tiy,
                                          float& accS, float& accC)
{
    const float2* src = d_L + off + (size_t)b*Hl*Hl;
    int ox = tix*32, oy = tiy*32;

    for (int i = ut; i < 36*36; i += 256) {
        int r = i/36, c = i%36;
        int gy = oy + r - 2, gx = ox + c - 2;
        float2 v = make_float2(0.f, 0.f);
        if (gy >= 0 && gy < Hl && gx >= 0 && gx < Hl)
            v = src[gy*Hl + gx];
        U.t[r][c] = v;
    }
    bar_sync(1);

    for (int i = ut; i < 36*32; i += 256) {
        int r = i >> 5, c = i & 31;
        float m1=0.f, m2=0.f, a11=0.f, a22=0.f, cr=0.f;
#pragma unroll
        for (int k = 0; k < 5; k++) {
            float g = c_g[k];
            float2 a = U.t[r][c+k];
            float ga = g*a.x, gq = g*a.y;
            m1 += ga; m2 += gq;
            a11 += ga*a.x; a22 += gq*a.y; cr += ga*a.y;
        }
        U.m12[r][c] = make_float2(m1, m2);
        U.x12[r][c] = make_float2(a11, a22);
        U.a12[r][c] = cr;
    }
    bar_sync(1);

    int tx = ut & 31, ty = ut >> 5;
    int y0 = ty*4;
    float2 mu[4], xx[4];
    float cr4[4];
#pragma unroll
    for (int j = 0; j < 4; j++) {
        mu[j] = make_float2(0.f, 0.f);
        xx[j] = make_float2(0.f, 0.f);
        cr4[j] = 0.f;
    }
#pragma unroll
    for (int k = 0; k < 8; k++) {
        float2 m = U.m12[y0+k][tx];
        float2 x = U.x12[y0+k][tx];
        float  a = U.a12[y0+k][tx];
#pragma unroll
        for (int j = 0; j < 4; j++) {
            int tap = k - j;
            if (tap >= 0 && tap < 5) {
                float w = c_g[tap];
                mu[j].x += w*m.x; mu[j].y += w*m.y;
                xx[j].x += w*x.x; xx[j].y += w*x.y;
                cr4[j]  += w*a;
            }
        }
    }
    const float C1 = 1e-4f, C2 = 9e-4f;
#pragma unroll
    for (int j = 0; j < 4; j++) {
        float s1  = xx[j].x - mu[j].x*mu[j].x;
        float s2  = xx[j].y - mu[j].y*mu[j].y;
        float s12 = cr4[j]  - mu[j].x*mu[j].y;
        float den  = s1 + s2 + C2;
        float num2 = 2.f*s12 + C2;
        accC += num2 / den;
        accS += ((2.f*mu[j].x*mu[j].y + C1) * num2) /
                ((mu[j].x*mu[j].x + mu[j].y*mu[j].y + C1) * den);
    }
}

__device__ __forceinline__ void reduce_unit(Unit& U, float& a, float& c, int ut)
{
    int lane = ut & 31, wid = ut >> 5;
    for (int o = 16; o; o >>= 1) {
        a += __shfl_down_sync(0xffffffffu, a, o);
        c += __shfl_down_sync(0xffffffffu, c, o);
    }
    if (lane == 0) { U.redS[wid] = a; U.redC[wid] = c; }
    bar_sync(1);
    if (wid == 0) {
        a = (lane < 8) ? U.redS[lane] : 0.f;
        c = (lane < 8) ? U.redC[lane] : 0.f;
        for (int o = 4; o; o >>= 1) {
            a += __shfl_down_sync(0xffffffffu, a, o);
            c += __shfl_down_sync(0xffffffffu, c, o);
        }
    }
    bar_sync(1);
}

// ---------------- L0 kernel: SSIM + hierarchical pool-ahead (L1..L4) --------
__global__ void __launch_bounds__(256)
k_ssim0()
{
    __shared__ Unit U;
    int b  = blockIdx.z;
    int ut = threadIdx.x;
    int tix = blockIdx.x, tiy = blockIdx.y;
    int ox = tix*32, oy = tiy*32;

    float aS = 0.f, aC = 0.f;
    ssim_core(U, ut, OFF0, 512, b, tix, tiy, aS, aC);
    reduce_unit(U, aS, aC, ut);
    if (ut == 0) {
        atomicAdd(&d_ssim_sum[b*5 + 0], aS);
        atomicAdd(&d_cs_sum[b*5 + 0], aC);
    }
    bar_sync(1);   // moment buffers dead -> reuse as pool scratch

    // pool scratch aliases (moment buffers are large enough)
    float2 (*P1)[16] = (float2(*)[16])U.m12;   // 16x16
    float2 (*P2)[8]  = (float2(*)[8]) U.x12;   // 8x8
    float2 (*P3)[4]  = (float2(*)[4]) U.a12;   // 4x4

    // L1 pool: 16x16, one px per thread
    {
        int rp = ut >> 4, cp = ut & 15;
        float2 q0 = U.t[2*rp+2][2*cp+2], q1 = U.t[2*rp+2][2*cp+3];
        float2 q2 = U.t[2*rp+3][2*cp+2], q3 = U.t[2*rp+3][2*cp+3];
        float2 pv = make_float2(0.25f*(q0.x+q1.x+q2.x+q3.x),
                                0.25f*(q0.y+q1.y+q2.y+q3.y));
        P1[rp][cp] = pv;
        d_L[(size_t)OFF1 + (size_t)b*256*256 + (size_t)((oy>>1)+rp)*256 + (ox>>1)+cp] = pv;
    }
    bar_sync(1);

    // L2 pool: 8x8
    if (ut < 64) {
        int rp = ut >> 3, cp = ut & 7;
        float2 q0 = P1[2*rp][2*cp],   q1 = P1[2*rp][2*cp+1];
        float2 q2 = P1[2*rp+1][2*cp], q3 = P1[2*rp+1][2*cp+1];
        float2 pv = make_float2(0.25f*(q0.x+q1.x+q2.x+q3.x),
                                0.25f*(q0.y+q1.y+q2.y+q3.y));
        P2[rp][cp] = pv;
        d_L[(size_t)OFF2 + (size_t)b*128*128 + (size_t)((oy>>2)+rp)*128 + (ox>>2)+cp] = pv;
    }
    bar_sync(1);

    // L3 pool: 4x4
    if (ut < 16) {
        int rp = ut >> 2, cp = ut & 3;
        float2 q0 = P2[2*rp][2*cp],   q1 = P2[2*rp][2*cp+1];
        float2 q2 = P2[2*rp+1][2*cp], q3 = P2[2*rp+1][2*cp+1];
        float2 pv = make_float2(0.25f*(q0.x+q1.x+q2.x+q3.x),
                                0.25f*(q0.y+q1.y+q2.y+q3.y));
        P3[rp][cp] = pv;
        d_L[(size_t)OFF3 + (size_t)b*64*64 + (size_t)((oy>>3)+rp)*64 + (ox>>3)+cp] = pv;
    }
    bar_sync(1);

    // L4 pool: 2x2
    if (ut < 4) {
        int rp = ut >> 1, cp = ut & 1;
        float2 q0 = P3[2*rp][2*cp],   q1 = P3[2*rp][2*cp+1];
        float2 q2 = P3[2*rp+1][2*cp], q3 = P3[2*rp+1][2*cp+1];
        float2 pv = make_float2(0.25f*(q0.x+q1.x+q2.x+q3.x),
                                0.25f*(q0.y+q1.y+q2.y+q3.y));
        d_L[(size_t)OFF4 + (size_t)b*32*32 + (size_t)((oy>>4)+rp)*32 + (ox>>4)+cp] = pv;
    }
}

// ---------------- batched SSIM for levels 1..4 (one launch) -----------------
// grid (85, 8): t<64 -> L1, t<80 -> L2, t<84 -> L3, t==84 -> L4
__global__ void __launch_bounds__(256)
k_ssimR()
{
    __shared__ Unit U;
    int b  = blockIdx.y;
    int t  = blockIdx.x;
    int ut = threadIdx.x;

    unsigned off; int Hl, lvl, tix, tiy;
    if (t < 64)      { off = OFF1; Hl = 256; lvl = 1; tix = t & 7;        tiy = t >> 3; }
    else if (t < 80) { off = OFF2; Hl = 128; lvl = 2; tix = (t-64) & 3;   tiy = (t-64) >> 2; }
    else if (t < 84) { off = OFF3; Hl = 64;  lvl = 3; tix = (t-80) & 1;   tiy = (t-80) >> 1; }
    else             { off = OFF4; Hl = 32;  lvl = 4; tix = 0;            tiy = 0; }

    float aS = 0.f, aC = 0.f;
    ssim_core(U, ut, off, Hl, b, tix, tiy, aS, aC);
    reduce_unit(U, aS, aC, ut);
    if (ut == 0) {
        atomicAdd(&d_ssim_sum[b*5 + lvl], aS);
        atomicAdd(&d_cs_sum[b*5 + lvl], aC);
    }
}

// ---------------- final: histogram L1 + assembly + state re-zero ------------
__global__ void __launch_bounds__(1024)
k_fin(float* __restrict__ out)
{
    __shared__ float red[32];
    __shared__ float l1img[8];
    __shared__ float msarr[8];
    int tid  = threadIdx.x;
    int lane = tid & 31, wid = tid >> 5;

    // per-image histogram L1: 8 block-reductions
    for (int img = 0; img < Bn; img++) {
        float s = (tid < 3*NBINS) ? fabsf((float)d_histd[img*3*NBINS + tid]) : 0.f;
        for (int o = 16; o; o >>= 1) s += __shfl_down_sync(0xffffffffu, s, o);
        if (lane == 0) red[wid] = s;
        __syncthreads();
        if (wid == 0) {
            s = red[lane];
            for (int o = 16; o; o >>= 1) s += __shfl_down_sync(0xffffffffu, s, o);
            if (lane == 0) l1img[img] = s * (1.f/768.f);
        }
        __syncthreads();
    }

    if (tid < 8) {
        const float wts[5] = {0.0448f, 0.2856f, 0.3001f, 0.2363f, 0.1333f};
        const float cnt[5] = {262144.f, 65536.f, 16384.f, 4096.f, 1024.f};
        float ms = 1.f;
        for (int l = 0; l < 4; l++) {
            float mcs = d_cs_sum[tid*5 + l] / cnt[l];
            ms *= powf((mcs + 1.f)*0.5f, wts[l]);
        }
        float mss4 = d_ssim_sum[tid*5 + 4] / cnt[4];
        ms *= powf((mss4 + 1.f)*0.5f, wts[4]);
        msarr[tid] = 1.f - ms;
    }
    __syncthreads();

    if (tid == 0) {
        float hist_loss = 0.f;
        for (int i = 0; i < 8; i++)
            hist_loss += exp2f((float)(i - 8)) * (l1img[i] + 1.f);
        float scaler = (float)NPIX / 20.f;
        hist_loss = hist_loss / 8.f / scaler;
        float lab_l1 = d_l1sum / (float)(Bn*3*NPIX);
        float sl = 0.f;
        for (int i = 0; i < 8; i++) sl += msarr[i];
        sl *= (1.f/8.f);
        out[0] = lab_l1 + hist_loss;
        out[1] = sl;
    }

    // re-zero accumulators for next graph replay
    for (int i = tid; i < Bn*3*NBINS; i += 1024) d_histd[i] = 0;
    if (tid < Bn*5) { d_ssim_sum[tid] = 0.f; d_cs_sum[tid] = 0.f; }
    if (tid == 0) d_l1sum = 0.f;
}

// ---------------- launch ------------------------------------------------------
extern "C" void kernel_launch(void* const* d_in, const int* in_sizes, int n_in,
                              void* d_out, int out_size)
{
    const float* pred = (const float*)d_in[1];
    const float* tgt  = (const float*)d_in[2];
    float* out = (float*)d_out;

    dim3 g1(128, Bn);
    k_lab<<<g1, 256>>>(pred, tgt);

    k_ssim0<<<dim3(16, 16, Bn), 256>>>();
    k_ssimR<<<dim3(85, Bn), 256>>>();
    k_fin<<<1, 1024>>>(out);
}

// round 16
// speedup vs baseline: 1.7403x; 1.0906x over previous
#include <cuda_runtime.h>
#include <math.h>

#define Bn    8
#define NPIX  (512*512)
#define NBINS 256

#define OFF0 0u
#define OFF1 2097152u
#define OFF2 2621440u
#define OFF3 2752512u
#define OFF4 2785280u

#define G0 0.12007823f
#define G1 0.23388087f
#define G2 0.29208180f
__device__ __constant__ float c_g[5] = {G0, G1, G2, G1, G0};

// interleaved pyramid: d_L[i] = (pred_L, tgt_L)
__device__ float2 d_L[2793472];
__device__ int    d_histd[Bn*3*NBINS];     // signed: pred minus tgt counts
__device__ float  d_l1sum;
__device__ float  d_ssim_sum[Bn*5];
__device__ float  d_cs_sum[Bn*5];
__device__ float  d_l1img[Bn];

__device__ __forceinline__ void bar_sync(int id)
{
    asm volatile("bar.sync %0, 256;" :: "r"(id) : "memory");
}

// ---------------- RGB -> normalized LAB -------------------------------------
__device__ __forceinline__ float srgb_lin(float x)
{
    if (x <= 0.04045f) return x * (1.f/12.92f);
    float y = (fmaxf(x, 1e-4f) + 0.055f) * (1.f/1.055f);
    return __powf(y, 2.4f);
}

__device__ __forceinline__ float f_lab(float t)
{
    const float e3 = 0.008856451679035631f;
    if (t <= e3) return t * (841.f/108.f) + (4.f/29.f);
    return __powf(fmaxf(t, 1e-4f), 1.f/3.f);
}

__device__ __forceinline__ void rgb2lab_norm(float r, float g, float b,
                                             float& L, float& A, float& Bc)
{
    float lr = srgb_lin(r), lg = srgb_lin(g), lb = srgb_lin(b);
    float X = lr*0.412453f + lg*0.357580f + lb*0.180423f;
    float Y = lr*0.212671f + lg*0.715160f + lb*0.072169f;
    float Z = lr*0.019334f + lg*0.119193f + lb*0.950227f;
    X *= (1.f/0.950456f);
    Z *= (1.f/1.088754f);
    float fx = f_lab(X), fy = f_lab(Y), fz = f_lab(Z);
    float Ll = 116.f*fy - 16.f;
    float Aa = 500.f*(fx - fy);
    float Bb = 200.f*(fy - fz);
    L  = __saturatef(Ll * 0.01f);
    A  = __saturatef(Aa*(1.f/220.f) + 0.5f);
    Bc = __saturatef(Bb*(1.f/220.f) + 0.5f);
}

__device__ __forceinline__ int bin_of(float v)
{
    int b = (int)(v * 256.f);
    return b > 255 ? 255 : b;
}

// ---------------- fused LAB + signed histogram + L1 + L store ---------------
// grid (128, 8) x 256 threads; 8 px/thread
__global__ void k_lab(const float* __restrict__ pred, const float* __restrict__ tgt)
{
    __shared__ int   sh[3*NBINS];
    __shared__ float red[8];
    int b   = blockIdx.y;
    int tid = threadIdx.x;

    for (int i = tid; i < 3*NBINS; i += 256) sh[i] = 0;
    __syncthreads();

    int* h0 = &sh[0];
    int* h1 = &sh[NBINS];
    int* h2 = &sh[2*NBINS];

    const size_t ibase = (size_t)b*3*NPIX;
    float l1acc = 0.f;

#pragma unroll
    for (int it = 0; it < 2; it++) {
        int p = blockIdx.x*2048 + it*1024 + tid*4;
        float4 pr = *(const float4*)(pred + ibase + p);
        float4 pg = *(const float4*)(pred + ibase + NPIX + p);
        float4 pb = *(const float4*)(pred + ibase + 2*NPIX + p);
        float4 tr = *(const float4*)(tgt  + ibase + p);
        float4 tg = *(const float4*)(tgt  + ibase + NPIX + p);
        float4 tb = *(const float4*)(tgt  + ibase + 2*NPIX + p);

        float* prf = &pr.x; float* pgf = &pg.x; float* pbf = &pb.x;
        float* trf = &tr.x; float* tgf = &tg.x; float* tbf = &tb.x;
        float pls[4], tls[4];
#pragma unroll
        for (int j = 0; j < 4; j++) {
            float pl, pa, pbc, tl, ta, tbc;
            rgb2lab_norm(prf[j], pgf[j], pbf[j], pl, pa, pbc);
            rgb2lab_norm(trf[j], tgf[j], tbf[j], tl, ta, tbc);
            pls[j] = pl; tls[j] = tl;
            atomicAdd(&h0[bin_of(pl)],   1);
            atomicAdd(&h1[bin_of(pa)],   1);
            atomicAdd(&h2[bin_of(pbc)],  1);
            atomicAdd(&h0[bin_of(tl)],  -1);
            atomicAdd(&h1[bin_of(ta)],  -1);
            atomicAdd(&h2[bin_of(tbc)], -1);
            l1acc += fabsf(pl-tl) + fabsf(pa-ta) + fabsf(pbc-tbc);
        }
        float4* dst = (float4*)&d_L[(size_t)b*NPIX + p];
        dst[0] = make_float4(pls[0], tls[0], pls[1], tls[1]);
        dst[1] = make_float4(pls[2], tls[2], pls[3], tls[3]);
    }
    __syncthreads();

    for (int i = tid; i < 3*NBINS; i += 256) {
        int hd = sh[i];
        if (hd) atomicAdd(&d_histd[b*3*NBINS + i], hd);
    }

    float v = l1acc;
    for (int o = 16; o; o >>= 1) v += __shfl_down_sync(0xffffffffu, v, o);
    int lane = tid & 31, wid = tid >> 5;
    if (lane == 0) red[wid] = v;
    __syncthreads();
    if (wid == 0) {
        v = (lane < 8) ? red[lane] : 0.f;
        for (int o = 4; o; o >>= 1) v += __shfl_down_sync(0xffffffffu, v, o);
        if (lane == 0) atomicAdd(&d_l1sum, v);
    }
}

// ---------------- 32x32 SSIM tile core (256 threads) ------------------------
struct Unit {
    float2 t[36][36];
    float2 m12[36][32];
    float2 x12[36][32];
    float  a12[36][32];
    float  redS[8], redC[8];
};

// SSIM moments + per-thread 4-output accumulation. No pooling.
__device__ __forceinline__ void ssim_core(Unit& U, int ut,
                                          unsigned off, int Hl, int b,
                                          int tix, int tiy,
                                          float& accS, float& accC)
{
    const float2* src = d_L + off + (size_t)b*Hl*Hl;
    int ox = tix*32, oy = tiy*32;

    for (int i = ut; i < 36*36; i += 256) {
        int r = i/36, c = i%36;
        int gy = oy + r - 2, gx = ox + c - 2;
        float2 v = make_float2(0.f, 0.f);
        if (gy >= 0 && gy < Hl && gx >= 0 && gx < Hl)
            v = src[gy*Hl + gx];
        U.t[r][c] = v;
    }
    bar_sync(1);

    for (int i = ut; i < 36*32; i += 256) {
        int r = i >> 5, c = i & 31;
        float m1=0.f, m2=0.f, a11=0.f, a22=0.f, cr=0.f;
#pragma unroll
        for (int k = 0; k < 5; k++) {
            float g = c_g[k];
            float2 a = U.t[r][c+k];
            float ga = g*a.x, gq = g*a.y;
            m1 += ga; m2 += gq;
            a11 += ga*a.x; a22 += gq*a.y; cr += ga*a.y;
        }
        U.m12[r][c] = make_float2(m1, m2);
        U.x12[r][c] = make_float2(a11, a22);
        U.a12[r][c] = cr;
    }
    bar_sync(1);

    int tx = ut & 31, ty = ut >> 5;
    int y0 = ty*4;
    float2 mu[4], xx[4];
    float cr4[4];
#pragma unroll
    for (int j = 0; j < 4; j++) {
        mu[j] = make_float2(0.f, 0.f);
        xx[j] = make_float2(0.f, 0.f);
        cr4[j] = 0.f;
    }
#pragma unroll
    for (int k = 0; k < 8; k++) {
        float2 m = U.m12[y0+k][tx];
        float2 x = U.x12[y0+k][tx];
        float  a = U.a12[y0+k][tx];
#pragma unroll
        for (int j = 0; j < 4; j++) {
            int tap = k - j;
            if (tap >= 0 && tap < 5) {
                float w = c_g[tap];
                mu[j].x += w*m.x; mu[j].y += w*m.y;
                xx[j].x += w*x.x; xx[j].y += w*x.y;
                cr4[j]  += w*a;
            }
        }
    }
    const float C1 = 1e-4f, C2 = 9e-4f;
#pragma unroll
    for (int j = 0; j < 4; j++) {
        float s1  = xx[j].x - mu[j].x*mu[j].x;
        float s2  = xx[j].y - mu[j].y*mu[j].y;
        float s12 = cr4[j]  - mu[j].x*mu[j].y;
        float den  = s1 + s2 + C2;
        float num2 = 2.f*s12 + C2;
        accC += num2 / den;
        accS += ((2.f*mu[j].x*mu[j].y + C1) * num2) /
                ((mu[j].x*mu[j].x + mu[j].y*mu[j].y + C1) * den);
    }
}

__device__ __forceinline__ void reduce_unit(Unit& U, float& a, float& c, int ut)
{
    int lane = ut & 31, wid = ut >> 5;
    for (int o = 16; o; o >>= 1) {
        a += __shfl_down_sync(0xffffffffu, a, o);
        c += __shfl_down_sync(0xffffffffu, c, o);
    }
    if (lane == 0) { U.redS[wid] = a; U.redC[wid] = c; }
    bar_sync(1);
    if (wid == 0) {
        a = (lane < 8) ? U.redS[lane] : 0.f;
        c = (lane < 8) ? U.redC[lane] : 0.f;
        for (int o = 4; o; o >>= 1) {
            a += __shfl_down_sync(0xffffffffu, a, o);
            c += __shfl_down_sync(0xffffffffu, c, o);
        }
    }
    bar_sync(1);
}

// ---------------- L0 kernel: SSIM + hierarchical pool-ahead (L1..L4) --------
__global__ void __launch_bounds__(256)
k_ssim0()
{
    __shared__ Unit U;
    int b  = blockIdx.z;
    int ut = threadIdx.x;
    int tix = blockIdx.x, tiy = blockIdx.y;
    int ox = tix*32, oy = tiy*32;

    float aS = 0.f, aC = 0.f;
    ssim_core(U, ut, OFF0, 512, b, tix, tiy, aS, aC);
    reduce_unit(U, aS, aC, ut);
    if (ut == 0) {
        atomicAdd(&d_ssim_sum[b*5 + 0], aS);
        atomicAdd(&d_cs_sum[b*5 + 0], aC);
    }
    bar_sync(1);   // moment buffers dead -> reuse as pool scratch

    // pool scratch aliases (moment buffers are large enough)
    float2 (*P1)[16] = (float2(*)[16])U.m12;   // 16x16
    float2 (*P2)[8]  = (float2(*)[8]) U.x12;   // 8x8
    float2 (*P3)[4]  = (float2(*)[4]) U.a12;   // 4x4

    // L1 pool: 16x16, one px per thread
    {
        int rp = ut >> 4, cp = ut & 15;
        float2 q0 = U.t[2*rp+2][2*cp+2], q1 = U.t[2*rp+2][2*cp+3];
        float2 q2 = U.t[2*rp+3][2*cp+2], q3 = U.t[2*rp+3][2*cp+3];
        float2 pv = make_float2(0.25f*(q0.x+q1.x+q2.x+q3.x),
                                0.25f*(q0.y+q1.y+q2.y+q3.y));
        P1[rp][cp] = pv;
        d_L[(size_t)OFF1 + (size_t)b*256*256 + (size_t)((oy>>1)+rp)*256 + (ox>>1)+cp] = pv;
    }
    bar_sync(1);

    // L2 pool: 8x8
    if (ut < 64) {
        int rp = ut >> 3, cp = ut & 7;
        float2 q0 = P1[2*rp][2*cp],   q1 = P1[2*rp][2*cp+1];
        float2 q2 = P1[2*rp+1][2*cp], q3 = P1[2*rp+1][2*cp+1];
        float2 pv = make_float2(0.25f*(q0.x+q1.x+q2.x+q3.x),
                                0.25f*(q0.y+q1.y+q2.y+q3.y));
        P2[rp][cp] = pv;
        d_L[(size_t)OFF2 + (size_t)b*128*128 + (size_t)((oy>>2)+rp)*128 + (ox>>2)+cp] = pv;
    }
    bar_sync(1);

    // L3 pool: 4x4
    if (ut < 16) {
        int rp = ut >> 2, cp = ut & 3;
        float2 q0 = P2[2*rp][2*cp],   q1 = P2[2*rp][2*cp+1];
        float2 q2 = P2[2*rp+1][2*cp], q3 = P2[2*rp+1][2*cp+1];
        float2 pv = make_float2(0.25f*(q0.x+q1.x+q2.x+q3.x),
                                0.25f*(q0.y+q1.y+q2.y+q3.y));
        P3[rp][cp] = pv;
        d_L[(size_t)OFF3 + (size_t)b*64*64 + (size_t)((oy>>3)+rp)*64 + (ox>>3)+cp] = pv;
    }
    bar_sync(1);

    // L4 pool: 2x2
    if (ut < 4) {
        int rp = ut >> 1, cp = ut & 1;
        float2 q0 = P3[2*rp][2*cp],   q1 = P3[2*rp][2*cp+1];
        float2 q2 = P3[2*rp+1][2*cp], q3 = P3[2*rp+1][2*cp+1];
        float2 pv = make_float2(0.25f*(q0.x+q1.x+q2.x+q3.x),
                                0.25f*(q0.y+q1.y+q2.y+q3.y));
        d_L[(size_t)OFF4 + (size_t)b*32*32 + (size_t)((oy>>4)+rp)*32 + (ox>>4)+cp] = pv;
    }
}

// ---------------- batched SSIM for levels 1..4 + per-image hist L1 ----------
// grid (86, 8): t<64 -> L1, t<80 -> L2, t<84 -> L3, t==84 -> L4, t==85 -> hist
__global__ void __launch_bounds__(256)
k_ssimR()
{
    __shared__ Unit U;
    int b  = blockIdx.y;
    int t  = blockIdx.x;
    int ut = threadIdx.x;

    if (t == 85) {
        // per-image histogram L1 reduction
        float s = 0.f;
        for (int i = ut; i < 3*NBINS; i += 256)
            s += fabsf((float)d_histd[b*3*NBINS + i]);
        int lane = ut & 31, wid = ut >> 5;
        for (int o = 16; o; o >>= 1) s += __shfl_down_sync(0xffffffffu, s, o);
        if (lane == 0) U.redS[wid] = s;
        __syncthreads();
        if (wid == 0) {
            s = (lane < 8) ? U.redS[lane] : 0.f;
            for (int o = 4; o; o >>= 1) s += __shfl_down_sync(0xffffffffu, s, o);
            if (lane == 0) d_l1img[b] = s * (1.f/768.f);
        }
        return;
    }

    unsigned off; int Hl, lvl, tix, tiy;
    if (t < 64)      { off = OFF1; Hl = 256; lvl = 1; tix = t & 7;        tiy = t >> 3; }
    else if (t < 80) { off = OFF2; Hl = 128; lvl = 2; tix = (t-64) & 3;   tiy = (t-64) >> 2; }
    else if (t < 84) { off = OFF3; Hl = 64;  lvl = 3; tix = (t-80) & 1;   tiy = (t-80) >> 1; }
    else             { off = OFF4; Hl = 32;  lvl = 4; tix = 0;            tiy = 0; }

    float aS = 0.f, aC = 0.f;
    ssim_core(U, ut, off, Hl, b, tix, tiy, aS, aC);
    reduce_unit(U, aS, aC, ut);
    if (ut == 0) {
        atomicAdd(&d_ssim_sum[b*5 + lvl], aS);
        atomicAdd(&d_cs_sum[b*5 + lvl], aC);
    }
}

// ---------------- final: tiny assembly + state re-zero ----------------------
__global__ void __launch_bounds__(1024)
k_fin(float* __restrict__ out)
{
    __shared__ float msarr[8];
    int tid = threadIdx.x;

    if (tid < 8) {
        const float wts[5] = {0.0448f, 0.2856f, 0.3001f, 0.2363f, 0.1333f};
        const float cnt[5] = {262144.f, 65536.f, 16384.f, 4096.f, 1024.f};
        float ms = 1.f;
        for (int l = 0; l < 4; l++) {
            float mcs = d_cs_sum[tid*5 + l] / cnt[l];
            ms *= powf((mcs + 1.f)*0.5f, wts[l]);
        }
        float mss4 = d_ssim_sum[tid*5 + 4] / cnt[4];
        ms *= powf((mss4 + 1.f)*0.5f, wts[4]);
        msarr[tid] = 1.f - ms;
    }
    __syncthreads();

    if (tid == 0) {
        float hist_loss = 0.f;
        for (int i = 0; i < 8; i++)
            hist_loss += exp2f((float)(i - 8)) * (d_l1img[i] + 1.f);
        float scaler = (float)NPIX / 20.f;
        hist_loss = hist_loss / 8.f / scaler;
        float lab_l1 = d_l1sum / (float)(Bn*3*NPIX);
        float sl = 0.f;
        for (int i = 0; i < 8; i++) sl += msarr[i];
        sl *= (1.f/8.f);
        out[0] = lab_l1 + hist_loss;
        out[1] = sl;
    }

    // re-zero accumulators for next graph replay
    for (int i = tid; i < Bn*3*NBINS; i += 1024) d_histd[i] = 0;
    if (tid < Bn*5) { d_ssim_sum[tid] = 0.f; d_cs_sum[tid] = 0.f; }
    if (tid == 0) d_l1sum = 0.f;
}

// ---------------- launch ------------------------------------------------------
extern "C" void kernel_launch(void* const* d_in, const int* in_sizes, int n_in,
                              void* d_out, int out_size)
{
    const float* pred = (const float*)d_in[1];
    const float* tgt  = (const float*)d_in[2];
    float* out = (float*)d_out;

    dim3 g1(128, Bn);
    k_lab<<<g1, 256>>>(pred, tgt);

    k_ssim0<<<dim3(16, 16, Bn), 256>>>();
    k_ssimR<<<dim3(86, Bn), 256>>>();
    k_fin<<<1, 1024>>>(out);
}